// round 9
// baseline (speedup 1.0000x reference)
#include <cuda_runtime.h>

// G2InvariantAttention — GB300 sm_103a — Round 9: single fused kernel.
//   * partial body = R3 verbatim (KSPLIT=8, occ cap 4, unroll 2, REDG accum
//     into 2MB per-query acc — best measured).
//   * NEW: epilogue fused via completion ticket. After REDs, each CTA fences
//     and thread0 atomicInc's a per-(bh,qblock) counter (wrap at KSPLIT-1 ->
//     self-resetting across graph replays). The LAST CTA of the group runs
//     the epilogue for its 256 queries while acc lines are hot in L2, then
//     zero-restores acc. Eliminates the second kernel (8.5us latency-bound).
// Exact math: oct_cross(k,k)=0, v==k, scale folded into q, no max-subtraction
// (logits bounded), linear partial combination (atomic order irrelevant at
// rel_err 1e-7 << 1e-3).

#define N_TOK   2048
#define N_HEAD  16
#define N_BATCH 2
#define DMODEL  128
#define TPB     256
#define KSPLIT  8
#define KCHUNK  (N_TOK / KSPLIT)      // 256 keys per CTA
#define NPAIR   (KCHUNK / 2)          // 128 key pairs
#define NGROUP  (N_BATCH * N_HEAD * (N_TOK / TPB))   // 256 ticket groups

typedef unsigned long long u64;

// Per-query accumulator: [B*H*N][8 floats] = 2 MB. Zero at load; winner CTA
// re-zeros after reading -> deterministic across graph replays.
__device__ float    g_acc[(size_t)N_BATCH * N_HEAD * N_TOK * 8];
// Completion tickets, one per (bh, qblock). atomicInc wraps at KSPLIT-1 ->
// returns to 0 after the last arrival; no explicit reset needed.
__device__ unsigned g_tick[NGROUP];

__device__ __forceinline__ u64 f2pack(float lo, float hi) {
    u64 r; asm("mov.b64 %0,{%1,%2};" : "=l"(r) : "f"(lo), "f"(hi)); return r;
}
__device__ __forceinline__ void f2unpack(u64 v, float& lo, float& hi) {
    asm("mov.b64 {%0,%1},%2;" : "=f"(lo), "=f"(hi) : "l"(v));
}
__device__ __forceinline__ u64 f2fma(u64 a, u64 b, u64 c) {
    u64 d; asm("fma.rn.f32x2 %0,%1,%2,%3;" : "=l"(d) : "l"(a), "l"(b), "l"(c)); return d;
}
__device__ __forceinline__ u64 f2mul(u64 a, u64 b) {
    u64 d; asm("mul.rn.f32x2 %0,%1,%2;" : "=l"(d) : "l"(a), "l"(b)); return d;
}
__device__ __forceinline__ u64 f2add(u64 a, u64 b) {
    u64 d; asm("add.rn.f32x2 %0,%1,%2;" : "=l"(d) : "l"(a), "l"(b)); return d;
}
__device__ __forceinline__ float fast_ex2(float x) {
    float r; asm("ex2.approx.f32 %0,%1;" : "=f"(r) : "f"(x)); return r;
}

__global__ void __launch_bounds__(TPB, 4) g2_attn_fused(
    const float* __restrict__ o, const float* __restrict__ mix,
    const float* __restrict__ alpha, const float* __restrict__ beta,
    float* __restrict__ out)
{
    // Pair-major layout: sP[pair][dim][parity], dims 0..6, slot 7 = pad.
    __shared__ float sP[NPAIR * 16];   // 8 KB
    __shared__ unsigned s_last;

    const int bh  = blockIdx.y;
    const int h   = bh & (N_HEAD - 1);
    const int b   = bh >> 4;
    const int ks  = blockIdx.z;
    const int tid = threadIdx.x;
    const float* obase = o + ((size_t)b * N_TOK) * DMODEL + h * 8;

    // Each thread loads one key of this CTA's slice, scatters into pair layout.
    {
        int j  = tid;                       // 0..255 == KCHUNK
        int jg = ks * KCHUNK + j;
        float4 v0 = *(const float4*)(obase + (size_t)jg * DMODEL);      // real,i0,i1,i2
        float4 v1 = *(const float4*)(obase + (size_t)jg * DMODEL + 4);  // i3..i6
        float* dst = sP + (j >> 1) * 16 + (j & 1);
        dst[0]  = v0.y;  dst[2]  = v0.z;  dst[4]  = v0.w;  dst[6]  = v1.x;
        dst[8]  = v1.y;  dst[10] = v1.z;  dst[12] = v1.w;  dst[14] = 0.0f;  // pad
    }
    __syncthreads();

    const int n = blockIdx.x * TPB + tid;

    // w_k = sigmoid(m0-m1); fold w_k * log2e / sqrt(7) into q.
    float m0 = mix[2 * h], m1 = mix[2 * h + 1];
    float wk = 1.0f / (1.0f + __expf(m1 - m0));
    const float coef = wk * 1.4426950408889634f * 0.3779644730092272f;

    float4 q0 = *(const float4*)(obase + (size_t)n * DMODEL);
    float4 q1 = *(const float4*)(obase + (size_t)n * DMODEL + 4);
    u64 qd0 = f2pack(q0.y * coef, q0.y * coef);
    u64 qd1 = f2pack(q0.z * coef, q0.z * coef);
    u64 qd2 = f2pack(q0.w * coef, q0.w * coef);
    u64 qd3 = f2pack(q1.x * coef, q1.x * coef);
    u64 qd4 = f2pack(q1.y * coef, q1.y * coef);
    u64 qd5 = f2pack(q1.z * coef, q1.z * coef);
    u64 qd6 = f2pack(q1.w * coef, q1.w * coef);

    u64 a0 = 0ULL, a1 = 0ULL, a2 = 0ULL, a3 = 0ULL, a4 = 0ULL, a5 = 0ULL, a6 = 0ULL;
    u64 l2 = 0ULL;   // packed (sum e even keys, sum e odd keys)

    unsigned sbase;
    asm("{ .reg .u64 t; cvta.to.shared.u64 t, %1; cvt.u32.u64 %0, t; }"
        : "=r"(sbase) : "l"(sP));

    unsigned addr = sbase;
    #pragma unroll 2
    for (int p = 0; p < NPAIR; p++, addr += 64) {
        u64 P0, P1, P2, P3, P4, P5, P6, P7;
        asm("ld.shared.v2.b64 {%0,%1},[%2];" : "=l"(P0), "=l"(P1) : "r"(addr));
        asm("ld.shared.v2.b64 {%0,%1},[%2];" : "=l"(P2), "=l"(P3) : "r"(addr + 16));
        asm("ld.shared.v2.b64 {%0,%1},[%2];" : "=l"(P4), "=l"(P5) : "r"(addr + 32));
        asm("ld.shared.v2.b64 {%0,%1},[%2];" : "=l"(P6), "=l"(P7) : "r"(addr + 48));
        (void)P7;
        u64 s = f2mul(qd0, P0);
        s = f2fma(qd1, P1, s);
        s = f2fma(qd2, P2, s);
        s = f2fma(qd3, P3, s);
        s = f2fma(qd4, P4, s);
        s = f2fma(qd5, P5, s);
        s = f2fma(qd6, P6, s);
        float sa, sb; f2unpack(s, sa, sb);
        float ea = fast_ex2(sa);
        float eb = fast_ex2(sb);
        u64 e2 = f2pack(ea, eb);
        a0 = f2fma(P0, e2, a0);
        a1 = f2fma(P1, e2, a1);
        a2 = f2fma(P2, e2, a2);
        a3 = f2fma(P3, e2, a3);
        a4 = f2fma(P4, e2, a4);
        a5 = f2fma(P5, e2, a5);
        a6 = f2fma(P6, e2, a6);
        l2 = f2add(l2, e2);
    }

    // Horizontal sums -> (y0..y6, l); REDG into the per-query accumulator.
    {
        float lo, hi, yv[8];
        f2unpack(a0, lo, hi); yv[0] = lo + hi;
        f2unpack(a1, lo, hi); yv[1] = lo + hi;
        f2unpack(a2, lo, hi); yv[2] = lo + hi;
        f2unpack(a3, lo, hi); yv[3] = lo + hi;
        f2unpack(a4, lo, hi); yv[4] = lo + hi;
        f2unpack(a5, lo, hi); yv[5] = lo + hi;
        f2unpack(a6, lo, hi); yv[6] = lo + hi;
        f2unpack(l2, lo, hi); yv[7] = lo + hi;

        float* acc = g_acc + (((size_t)bh * N_TOK + n) << 3);
        #pragma unroll
        for (int i = 0; i < 8; i++) atomicAdd(acc + i, yv[i]);
    }

    // ---- Completion ticket: last CTA of this (bh, qblock) runs the epilogue.
    __threadfence();          // release: our REDs visible before the inc
    __syncthreads();          // all threads' REDs issued+fenced
    if (tid == 0) {
        unsigned c = blockIdx.y * (N_TOK / TPB) + blockIdx.x;
        // wraps: old == KSPLIT-1 -> counter returns to 0 (replay-clean)
        unsigned old = atomicInc(&g_tick[c], KSPLIT - 1);
        s_last = (old == KSPLIT - 1) ? 1u : 0u;
    }
    __syncthreads();
    if (!s_last) return;

    __threadfence();          // acquire: see all other CTAs' REDs

    // ---- Epilogue for this CTA's 256 queries (q already loaded: q0,q1).
    float* acc = g_acc + (((size_t)bh * N_TOK + n) << 3);
    float4 w0 = *(const float4*)(acc);
    float4 w1 = *(const float4*)(acc + 4);
    float y[7] = {w0.x, w0.y, w0.z, w0.w, w1.x, w1.y, w1.z};
    float l = w1.w;

    // Zero-restore for the next graph replay.
    *(float4*)(acc)     = make_float4(0.f, 0.f, 0.f, 0.f);
    *(float4*)(acc + 4) = make_float4(0.f, 0.f, 0.f, 0.f);

    float rinv = 1.0f / l;
    #pragma unroll
    for (int i = 0; i < 7; i++) y[i] *= rinv;

    float real = q0.x;
    float qo[7] = {q0.y, q0.z, q0.w, q1.x, q1.y, q1.z, q1.w};

    // Octonion cross product c = qo x y.
    float c[7];
    #pragma unroll
    for (int i = 0; i < 7; i++) c[i] = 0.0f;
    const int FI[7] = {0, 0, 0, 1, 1, 2, 2};
    const int FJ[7] = {1, 3, 6, 3, 4, 3, 5};
    const int FK[7] = {2, 4, 5, 5, 6, 6, 4};
    #pragma unroll
    for (int t = 0; t < 7; t++) {
        int i = FI[t], j = FJ[t], k = FK[t];
        c[k] += qo[i] * y[j] - qo[j] * y[i];
        c[i] += qo[j] * y[k] - qo[k] * y[j];
        c[j] += qo[k] * y[i] - qo[i] * y[k];
    }

    float av = 1.0f / (1.0f + __expf(-alpha[h]));
    float bv = tanhf(beta[h]);

    float im[7];
    float ns = real * real;
    #pragma unroll
    for (int i = 0; i < 7; i++) {
        im[i] = av * y[i] + bv * c[i];
        ns += im[i] * im[i];
    }
    float inv = 1.0f / fmaxf(sqrtf(ns), 1e-12f);

    float* op = out + ((size_t)(b * N_TOK + n)) * DMODEL + h * 8;
    *(float4*)(op)     = make_float4(real * inv, im[0] * inv, im[1] * inv, im[2] * inv);
    *(float4*)(op + 4) = make_float4(im[3] * inv, im[4] * inv, im[5] * inv, im[6] * inv);
}

extern "C" void kernel_launch(void* const* d_in, const int* in_sizes, int n_in,
                              void* d_out, int out_size) {
    const float* o     = (const float*)d_in[0];
    const float* mix   = (const float*)d_in[1];
    const float* alpha = (const float*)d_in[2];
    const float* beta  = (const float*)d_in[3];
    float* out = (float*)d_out;
    (void)in_sizes; (void)n_in; (void)out_size;

    dim3 grid(N_TOK / TPB, N_BATCH * N_HEAD, KSPLIT);   // (8, 32, 8) = 2048 CTAs
    g2_attn_fused<<<grid, TPB>>>(o, mix, alpha, beta, out);
}

// round 10
// speedup vs baseline: 1.0918x; 1.0918x over previous
#include <cuda_runtime.h>

// G2InvariantAttention — GB300 sm_103a — Round 10: R8 base (best: 101.1us),
// two independent changes:
//   * partial: unroll 2 -> 4 at occ cap 4 (4 independent score chains/warp;
//     regs ~56 < 64 cap, no spill — R4's failure was the occ-6/42-reg cap).
//   * combine: TPB 256 -> 64 (1024 CTAs = 6.9 waves, kills the 73%-empty
//     second wave of the 256-CTA launch).
// Exact math: oct_cross(k,k)=0, v==k, scale folded into q, no max-subtraction
// (logits bounded), linear partial combination via REDG into 2MB acc.

#define N_TOK   2048
#define N_HEAD  16
#define N_BATCH 2
#define DMODEL  128
#define TPB     256
#define CTPB    64                    // combine threads per block
#define KSPLIT  8
#define KCHUNK  (N_TOK / KSPLIT)      // 256 keys per CTA
#define NPAIR   (KCHUNK / 2)          // 128 key pairs

typedef unsigned long long u64;

// Per-query accumulator: [B*H*N][8 floats] = 2 MB. Zero-init at module load;
// the combine kernel re-zeros after reading -> deterministic across replays.
__device__ float g_acc[(size_t)N_BATCH * N_HEAD * N_TOK * 8];

__device__ __forceinline__ u64 f2pack(float lo, float hi) {
    u64 r; asm("mov.b64 %0,{%1,%2};" : "=l"(r) : "f"(lo), "f"(hi)); return r;
}
__device__ __forceinline__ void f2unpack(u64 v, float& lo, float& hi) {
    asm("mov.b64 {%0,%1},%2;" : "=f"(lo), "=f"(hi) : "l"(v));
}
__device__ __forceinline__ u64 f2fma(u64 a, u64 b, u64 c) {
    u64 d; asm("fma.rn.f32x2 %0,%1,%2,%3;" : "=l"(d) : "l"(a), "l"(b), "l"(c)); return d;
}
__device__ __forceinline__ u64 f2mul(u64 a, u64 b) {
    u64 d; asm("mul.rn.f32x2 %0,%1,%2;" : "=l"(d) : "l"(a), "l"(b)); return d;
}
__device__ __forceinline__ u64 f2add(u64 a, u64 b) {
    u64 d; asm("add.rn.f32x2 %0,%1,%2;" : "=l"(d) : "l"(a), "l"(b)); return d;
}
__device__ __forceinline__ float fast_ex2(float x) {
    float r; asm("ex2.approx.f32 %0,%1;" : "=f"(r) : "f"(x)); return r;
}

// ---------------- Kernel 1: partial attention over a 256-key slice ----------
__global__ void __launch_bounds__(TPB, 4) g2_attn_partial(
    const float* __restrict__ o, const float* __restrict__ mix)
{
    // Pair-major layout: sP[pair][dim][parity], dims 0..6, slot 7 = pad.
    __shared__ float sP[NPAIR * 16];   // 8 KB

    const int bh  = blockIdx.y;
    const int h   = bh & (N_HEAD - 1);
    const int b   = bh >> 4;
    const int ks  = blockIdx.z;
    const int tid = threadIdx.x;
    const float* obase = o + ((size_t)b * N_TOK) * DMODEL + h * 8;

    // Each thread loads one key of this CTA's slice, scatters into pair layout.
    {
        int j  = tid;                       // 0..255 == KCHUNK
        int jg = ks * KCHUNK + j;
        float4 v0 = *(const float4*)(obase + (size_t)jg * DMODEL);      // real,i0,i1,i2
        float4 v1 = *(const float4*)(obase + (size_t)jg * DMODEL + 4);  // i3..i6
        float* dst = sP + (j >> 1) * 16 + (j & 1);
        dst[0]  = v0.y;  dst[2]  = v0.z;  dst[4]  = v0.w;  dst[6]  = v1.x;
        dst[8]  = v1.y;  dst[10] = v1.z;  dst[12] = v1.w;  dst[14] = 0.0f;  // pad
    }
    __syncthreads();

    const int n = blockIdx.x * TPB + tid;

    // w_k = sigmoid(m0-m1); fold w_k * log2e / sqrt(7) into q.
    float m0 = mix[2 * h], m1 = mix[2 * h + 1];
    float wk = 1.0f / (1.0f + __expf(m1 - m0));
    const float coef = wk * 1.4426950408889634f * 0.3779644730092272f;

    float4 q0 = *(const float4*)(obase + (size_t)n * DMODEL);
    float4 q1 = *(const float4*)(obase + (size_t)n * DMODEL + 4);
    u64 qd0 = f2pack(q0.y * coef, q0.y * coef);
    u64 qd1 = f2pack(q0.z * coef, q0.z * coef);
    u64 qd2 = f2pack(q0.w * coef, q0.w * coef);
    u64 qd3 = f2pack(q1.x * coef, q1.x * coef);
    u64 qd4 = f2pack(q1.y * coef, q1.y * coef);
    u64 qd5 = f2pack(q1.z * coef, q1.z * coef);
    u64 qd6 = f2pack(q1.w * coef, q1.w * coef);

    u64 a0 = 0ULL, a1 = 0ULL, a2 = 0ULL, a3 = 0ULL, a4 = 0ULL, a5 = 0ULL, a6 = 0ULL;
    u64 l2 = 0ULL;   // packed (sum e even keys, sum e odd keys)

    unsigned sbase;
    asm("{ .reg .u64 t; cvta.to.shared.u64 t, %1; cvt.u32.u64 %0, t; }"
        : "=r"(sbase) : "l"(sP));

    unsigned addr = sbase;
    #pragma unroll 4
    for (int p = 0; p < NPAIR; p++, addr += 64) {
        u64 P0, P1, P2, P3, P4, P5, P6, P7;
        asm("ld.shared.v2.b64 {%0,%1},[%2];" : "=l"(P0), "=l"(P1) : "r"(addr));
        asm("ld.shared.v2.b64 {%0,%1},[%2];" : "=l"(P2), "=l"(P3) : "r"(addr + 16));
        asm("ld.shared.v2.b64 {%0,%1},[%2];" : "=l"(P4), "=l"(P5) : "r"(addr + 32));
        asm("ld.shared.v2.b64 {%0,%1},[%2];" : "=l"(P6), "=l"(P7) : "r"(addr + 48));
        (void)P7;
        u64 s = f2mul(qd0, P0);
        s = f2fma(qd1, P1, s);
        s = f2fma(qd2, P2, s);
        s = f2fma(qd3, P3, s);
        s = f2fma(qd4, P4, s);
        s = f2fma(qd5, P5, s);
        s = f2fma(qd6, P6, s);
        float sa, sb; f2unpack(s, sa, sb);
        float ea = fast_ex2(sa);
        float eb = fast_ex2(sb);
        u64 e2 = f2pack(ea, eb);
        a0 = f2fma(P0, e2, a0);
        a1 = f2fma(P1, e2, a1);
        a2 = f2fma(P2, e2, a2);
        a3 = f2fma(P3, e2, a3);
        a4 = f2fma(P4, e2, a4);
        a5 = f2fma(P5, e2, a5);
        a6 = f2fma(P6, e2, a6);
        l2 = f2add(l2, e2);
    }

    // Horizontal sums -> (y0..y6, l); accumulate into per-query slot via REDG.
    float lo, hi, y[8];
    f2unpack(a0, lo, hi); y[0] = lo + hi;
    f2unpack(a1, lo, hi); y[1] = lo + hi;
    f2unpack(a2, lo, hi); y[2] = lo + hi;
    f2unpack(a3, lo, hi); y[3] = lo + hi;
    f2unpack(a4, lo, hi); y[4] = lo + hi;
    f2unpack(a5, lo, hi); y[5] = lo + hi;
    f2unpack(a6, lo, hi); y[6] = lo + hi;
    f2unpack(l2, lo, hi); y[7] = lo + hi;

    float* acc = g_acc + (((size_t)bh * N_TOK + n) << 3);
    #pragma unroll
    for (int i = 0; i < 8; i++) atomicAdd(acc + i, y[i]);   // RED, no return
}

// ---------------- Kernel 2: per-query epilogue (64-thread CTAs) -------------
__global__ void __launch_bounds__(CTPB) g2_attn_combine(
    const float* __restrict__ o,
    const float* __restrict__ alpha, const float* __restrict__ beta,
    float* __restrict__ out)
{
    const int qi = blockIdx.x * CTPB + threadIdx.x;  // 0 .. B*H*N-1
    const int bh = qi >> 11;
    const int n  = qi & (N_TOK - 1);
    const int h  = bh & (N_HEAD - 1);
    const int b  = bh >> 4;

    float* acc = g_acc + ((size_t)qi << 3);
    float4 w0 = *(const float4*)(acc);
    float4 w1 = *(const float4*)(acc + 4);
    float y[7] = {w0.x, w0.y, w0.z, w0.w, w1.x, w1.y, w1.z};
    float l = w1.w;

    // Restore zeros for the next graph replay (deterministic state).
    *(float4*)(acc)     = make_float4(0.f, 0.f, 0.f, 0.f);
    *(float4*)(acc + 4) = make_float4(0.f, 0.f, 0.f, 0.f);

    float rinv = 1.0f / l;
    #pragma unroll
    for (int i = 0; i < 7; i++) y[i] *= rinv;

    const float* obase = o + ((size_t)b * N_TOK) * DMODEL + h * 8;
    float4 q0 = *(const float4*)(obase + (size_t)n * DMODEL);
    float4 q1 = *(const float4*)(obase + (size_t)n * DMODEL + 4);
    float real = q0.x;
    float qo[7] = {q0.y, q0.z, q0.w, q1.x, q1.y, q1.z, q1.w};

    // Octonion cross product c = qo x y.
    float c[7];
    #pragma unroll
    for (int i = 0; i < 7; i++) c[i] = 0.0f;
    const int FI[7] = {0, 0, 0, 1, 1, 2, 2};
    const int FJ[7] = {1, 3, 6, 3, 4, 3, 5};
    const int FK[7] = {2, 4, 5, 5, 6, 6, 4};
    #pragma unroll
    for (int t = 0; t < 7; t++) {
        int i = FI[t], j = FJ[t], k = FK[t];
        c[k] += qo[i] * y[j] - qo[j] * y[i];
        c[i] += qo[j] * y[k] - qo[k] * y[j];
        c[j] += qo[k] * y[i] - qo[i] * y[k];
    }

    float av = 1.0f / (1.0f + __expf(-alpha[h]));
    float bv = tanhf(beta[h]);

    float im[7];
    float ns = real * real;
    #pragma unroll
    for (int i = 0; i < 7; i++) {
        im[i] = av * y[i] + bv * c[i];
        ns += im[i] * im[i];
    }
    float inv = 1.0f / fmaxf(sqrtf(ns), 1e-12f);

    float* op = out + ((size_t)(b * N_TOK + n)) * DMODEL + h * 8;
    *(float4*)(op)     = make_float4(real * inv, im[0] * inv, im[1] * inv, im[2] * inv);
    *(float4*)(op + 4) = make_float4(im[3] * inv, im[4] * inv, im[5] * inv, im[6] * inv);
}

extern "C" void kernel_launch(void* const* d_in, const int* in_sizes, int n_in,
                              void* d_out, int out_size) {
    const float* o     = (const float*)d_in[0];
    const float* mix   = (const float*)d_in[1];
    const float* alpha = (const float*)d_in[2];
    const float* beta  = (const float*)d_in[3];
    float* out = (float*)d_out;
    (void)in_sizes; (void)n_in; (void)out_size;

    dim3 grid1(N_TOK / TPB, N_BATCH * N_HEAD, KSPLIT);   // (8, 32, 8) = 2048 CTAs
    g2_attn_partial<<<grid1, TPB>>>(o, mix);

    int total = N_BATCH * N_HEAD * N_TOK;                // 65536 queries
    g2_attn_combine<<<total / CTPB, CTPB>>>(o, alpha, beta, out);  // 1024 CTAs
}